// round 15
// baseline (speedup 1.0000x reference)
#include <cuda_runtime.h>

// x: (B=16, L=8192, F=512) float32, contiguous.
// y[b,t,:] = x[b,t+1,:] - x[b,t,:]   for t < L-1
// y[b,L-1,:] = x[b,L-1,:] - x[b,L-2,:]
//
// Sweep cell: THREADS=512, ITEMS=4 (last corner of the block-size x unroll
// matrix). 16 warps/CTA + 8 front-batched LDG.128/thread. Default cache
// policy throughout (hints regressed in R9/R10).

static constexpr int F4_PER_ROW = 512 / 4;   // 128
static constexpr int L_STEPS    = 8192;
static constexpr int ITEMS      = 4;
static constexpr int THREADS    = 512;

__global__ void __launch_bounds__(THREADS)
diff1d_kernel(const float4* __restrict__ x, float4* __restrict__ y, int n4)
{
    int base = blockIdx.x * (THREADS * ITEMS) + threadIdx.x;

    int    jj[ITEMS];
    float  ss[ITEMS];
    float4 a[ITEMS];
    float4 b[ITEMS];

    // Index math + front-batched loads (8 independent LDG.128)
    #pragma unroll
    for (int i = 0; i < ITEMS; i++) {
        int j     = base + i * THREADS;
        int t     = (j >> 7) & (L_STEPS - 1);
        bool last = (t == L_STEPS - 1);
        int jb    = j + (last ? -F4_PER_ROW : F4_PER_ROW);
        jj[i]     = j;
        ss[i]     = last ? -1.0f : 1.0f;
        a[i]      = x[j];
        b[i]      = x[jb];
    }

    #pragma unroll
    for (int i = 0; i < ITEMS; i++) {
        float4 r;
        r.x = ss[i] * (b[i].x - a[i].x);
        r.y = ss[i] * (b[i].y - a[i].y);
        r.z = ss[i] * (b[i].z - a[i].z);
        r.w = ss[i] * (b[i].w - a[i].w);
        y[jj[i]] = r;
    }
}

extern "C" void kernel_launch(void* const* d_in, const int* in_sizes, int n_in,
                              void* d_out, int out_size)
{
    const float4* x = (const float4*)d_in[0];
    float4* y = (float4*)d_out;
    int n4 = out_size / 4;               // 16,777,216 float4

    int tile   = THREADS * ITEMS;        // 2048 float4 per block
    int blocks = (n4 + tile - 1) / tile; // 8192, exact
    diff1d_kernel<<<blocks, THREADS>>>(x, y, n4);
}

// round 17
// speedup vs baseline: 1.0039x; 1.0039x over previous
#include <cuda_runtime.h>

// x: (B=16, L=8192, F=512) float32, contiguous.
// y[b,t,:] = x[b,t+1,:] - x[b,t,:]   for t < L-1
// y[b,L-1,:] = x[b,L-1,:] - x[b,L-2,:]
//
// FINAL kernel (best measured: 73.9us, DRAM 82.0%, R13 config).
// Flat float4 scheme, THREADS=512, ITEMS=2: 16 warps/CTA, 4 front-batched
// independent LDG.128 per thread, regs 24, occ ~76%. Branchless edge via
// sign flip. Default cache policy (__ldcs/__stcs both measured as
// regressions on sm_103a). Sweep over {structure, unroll, block size,
// cache hints} showed all hint-free variants within 1.5us of the
// 1R+1W streaming ceiling (~82% of 8TB/s spec).

static constexpr int F4_PER_ROW = 512 / 4;   // 128
static constexpr int L_STEPS    = 8192;
static constexpr int ITEMS      = 2;
static constexpr int THREADS    = 512;

__global__ void __launch_bounds__(THREADS)
diff1d_kernel(const float4* __restrict__ x, float4* __restrict__ y, int n4)
{
    int base = blockIdx.x * (THREADS * ITEMS) + threadIdx.x;

    int    jj[ITEMS];
    float  ss[ITEMS];
    float4 a[ITEMS];
    float4 b[ITEMS];

    // Index math + front-batched loads (4 independent LDG.128)
    #pragma unroll
    for (int i = 0; i < ITEMS; i++) {
        int j     = base + i * THREADS;
        int t     = (j >> 7) & (L_STEPS - 1);
        bool last = (t == L_STEPS - 1);
        int jb    = j + (last ? -F4_PER_ROW : F4_PER_ROW);
        jj[i]     = j;
        ss[i]     = last ? -1.0f : 1.0f;
        a[i]      = x[j];
        b[i]      = x[jb];
    }

    #pragma unroll
    for (int i = 0; i < ITEMS; i++) {
        float4 r;
        r.x = ss[i] * (b[i].x - a[i].x);
        r.y = ss[i] * (b[i].y - a[i].y);
        r.z = ss[i] * (b[i].z - a[i].z);
        r.w = ss[i] * (b[i].w - a[i].w);
        y[jj[i]] = r;
    }
}

extern "C" void kernel_launch(void* const* d_in, const int* in_sizes, int n_in,
                              void* d_out, int out_size)
{
    const float4* x = (const float4*)d_in[0];
    float4* y = (float4*)d_out;
    int n4 = out_size / 4;               // 16,777,216 float4

    int tile   = THREADS * ITEMS;        // 1024 float4 per block
    int blocks = (n4 + tile - 1) / tile; // 16384, exact
    diff1d_kernel<<<blocks, THREADS>>>(x, y, n4);
}